// round 13
// baseline (speedup 1.0000x reference)
#include <cuda_runtime.h>
#include <cuda_bf16.h>
#include <math.h>
#include <stdint.h>

#define Bdim 64
#define Sdim 512
#define Fdim 512
#define Hdim 1024

// ---------------- scratch (static device globals; no runtime allocation) ----
__device__ float g_xp[(size_t)Bdim * Sdim * Hdim];    // xp layer 0 (from x)
__device__ float g_xp2[(size_t)Bdim * Sdim * Hdim];   // xp layer 1 [t][b][H]
__device__ __nv_bfloat16 g_hh1[2][Bdim * Hdim];       // layer-0 hidden hi, [b][k]
__device__ __nv_bfloat16 g_hl1[2][Bdim * Hdim];       // layer-0 hidden lo
__device__ __nv_bfloat16 g_hh2[2][Bdim * Hdim];       // layer-1 hidden hi
__device__ __nv_bfloat16 g_hl2[2][Bdim * Hdim];       // layer-1 hidden lo
__device__ unsigned g_barG_cnt = 0; __device__ unsigned g_barG_gen = 0;
__device__ unsigned g_barA_cnt = 0; __device__ unsigned g_barA_gen = 0;
__device__ unsigned g_barB_cnt = 0; __device__ unsigned g_barB_gen = 0;
__device__ unsigned g_stepA = 0;    // A publications: 64 per completed xp2 step

static __device__ __forceinline__ unsigned smem_u32(const void* p) {
    return (unsigned)__cvta_generic_to_shared(p);
}

// ---------------- cohort barrier: scoped release/acquire --------------------
static __device__ __forceinline__ void grid_sync_p(unsigned* cnt, unsigned* gen,
                                                   int nblocks) {
    __syncthreads();
    if (threadIdx.x == 0) {
        unsigned g;
        asm volatile("ld.relaxed.gpu.global.u32 %0, [%1];" : "=r"(g) : "l"(gen));
        unsigned old;
        asm volatile("atom.acq_rel.gpu.global.add.u32 %0, [%1], 1;"
                     : "=r"(old) : "l"(cnt) : "memory");
        if (old == (unsigned)(nblocks - 1)) {
            asm volatile("st.relaxed.gpu.global.u32 [%0], %1;"
                         :: "l"(cnt), "r"(0u) : "memory");
            asm volatile("st.release.gpu.global.u32 [%0], %1;"
                         :: "l"(gen), "r"(g + 1) : "memory");
        } else {
            unsigned cur;
            do {
                asm volatile("ld.acquire.gpu.global.u32 %0, [%1];"
                             : "=r"(cur) : "l"(gen) : "memory");
            } while (cur == g);
        }
    }
    __syncthreads();
}

// ---------------- mma.sync helpers ------------------------------------------
static __device__ __forceinline__ void ldsm_x4(uint32_t addr, uint32_t* r) {
    asm volatile("ldmatrix.sync.aligned.m8n8.x4.shared.b16 {%0,%1,%2,%3}, [%4];"
                 : "=r"(r[0]), "=r"(r[1]), "=r"(r[2]), "=r"(r[3]) : "r"(addr));
}
static __device__ __forceinline__ void mma16816(float* c, const uint32_t* a,
                                                const uint32_t* b) {
    asm volatile("mma.sync.aligned.m16n8k16.row.col.f32.bf16.bf16.f32 "
                 "{%0,%1,%2,%3}, {%4,%5,%6,%7}, {%8,%9}, {%0,%1,%2,%3};"
                 : "+f"(c[0]), "+f"(c[1]), "+f"(c[2]), "+f"(c[3])
                 : "r"(a[0]), "r"(a[1]), "r"(a[2]), "r"(a[3]),
                   "r"(b[0]), "r"(b[1]));
}
static __device__ __forceinline__ void split_bf16(float4 v, uint2& hi, uint2& lo) {
    __nv_bfloat162 h01 = __floats2bfloat162_rn(v.x, v.y);
    __nv_bfloat162 h23 = __floats2bfloat162_rn(v.z, v.w);
    __nv_bfloat162 l01 = __floats2bfloat162_rn(v.x - __low2float(h01),
                                               v.y - __high2float(h01));
    __nv_bfloat162 l23 = __floats2bfloat162_rn(v.z - __low2float(h23),
                                               v.w - __high2float(h23));
    hi = make_uint2(*(unsigned*)&h01, *(unsigned*)&h23);
    lo = make_uint2(*(unsigned*)&l01, *(unsigned*)&l23);
}
// 2-value split -> packed bf16x2 hi/lo words
static __device__ __forceinline__ void split2_bf16(float v0, float v1,
                                                   unsigned& hi, unsigned& lo) {
    __nv_bfloat162 h = __floats2bfloat162_rn(v0, v1);
    __nv_bfloat162 l = __floats2bfloat162_rn(v0 - __low2float(h),
                                             v1 - __high2float(h));
    hi = *(unsigned*)&h;
    lo = *(unsigned*)&l;
}

// ============================================================================
// xproj kernel for layer-0 xp (proven R7 body): out = A@Wt^T + ba + bb
// ============================================================================
#define SW128(o) ((o) ^ (((o) >> 3) & 0x70))
#define XP_OFF_BIAS 0
#define XP_OFF_AH   1024
#define XP_OFF_AL   (XP_OFF_AH + 16384)
#define XP_OFF_BH   (XP_OFF_AL + 16384)
#define XP_OFF_BL   (XP_OFF_BH + 16384)
#define XP_SMEM     (XP_OFF_BL + 16384)

static __device__ __forceinline__ uint32_t lm_addr(uint32_t base, int r, int ck) {
    return base + r * 128 + ((ck ^ (r & 7)) << 4);
}

template <int K>
__global__ void __launch_bounds__(256, 2) xproj_mma_kernel(
    const float* __restrict__ A, const float* __restrict__ Wt,
    const float* __restrict__ ba, const float* __restrict__ bb,
    float* __restrict__ out)
{
    extern __shared__ __align__(1024) char xsm[];
    const uint32_t sb = smem_u32(xsm);
    const int tid = threadIdx.x;
    const int wid = tid >> 5;
    const int lane = tid & 31;
    const int wm = wid & 3;
    const int wn = wid >> 2;
    const int m0 = blockIdx.y * 128;
    const int n0 = blockIdx.x * 128;

    float* sbias = (float*)(xsm + XP_OFF_BIAS);
    if (tid < 128) sbias[tid] = ba[n0 + tid] + bb[n0 + tid];

    float acc[2][8][4];
#pragma unroll
    for (int mt = 0; mt < 2; mt++)
#pragma unroll
        for (int nt = 0; nt < 8; nt++)
#pragma unroll
            for (int i = 0; i < 4; i++) acc[mt][nt][i] = 0.0f;

    const int NKT = K / 64;
#pragma unroll 1
    for (int kt = 0; kt < NKT; kt++) {
        __syncthreads();
        const float* Asrc = A + (size_t)m0 * K + kt * 64;
        const float* Bsrc = Wt + (size_t)n0 * K + kt * 64;
#pragma unroll
        for (int r = 0; r < 8; r++) {
            int idx = r * 256 + tid;
            int row = idx >> 4;
            int c4 = idx & 15;
            int sw = SW128(row * 128 + c4 * 8);
            uint2 hi, lo;
            split_bf16(*(const float4*)&Asrc[(size_t)row * K + c4 * 4], hi, lo);
            *(uint2*)(xsm + XP_OFF_AH + sw) = hi;
            *(uint2*)(xsm + XP_OFF_AL + sw) = lo;
            split_bf16(*(const float4*)&Bsrc[(size_t)row * K + c4 * 4], hi, lo);
            *(uint2*)(xsm + XP_OFF_BH + sw) = hi;
            *(uint2*)(xsm + XP_OFF_BL + sw) = lo;
        }
        __syncthreads();

        const int asub = lane >> 3;
        const int arow = (asub & 1) * 8 + (lane & 7);
        const int ack = asub >> 1;
        const int brow = ((lane >> 4) & 1) * 8 + (lane & 7);
        const int bck = (lane >> 3) & 1;

#pragma unroll
        for (int p = 0; p < 3; p++) {
            uint32_t aBase = sb + ((p == 2) ? XP_OFF_AL : XP_OFF_AH);
            uint32_t bBase = sb + ((p == 1) ? XP_OFF_BL : XP_OFF_BH);
#pragma unroll
            for (int kk = 0; kk < 4; kk++) {
                uint32_t afrag[2][4], bfrag[8][2];
#pragma unroll
                for (int mt = 0; mt < 2; mt++)
                    ldsm_x4(lm_addr(aBase, wm * 32 + mt * 16 + arow, kk * 2 + ack),
                            afrag[mt]);
#pragma unroll
                for (int np = 0; np < 4; np++) {
                    uint32_t r4[4];
                    ldsm_x4(lm_addr(bBase, wn * 64 + np * 16 + brow, kk * 2 + bck), r4);
                    bfrag[np * 2][0] = r4[0]; bfrag[np * 2][1] = r4[1];
                    bfrag[np * 2 + 1][0] = r4[2]; bfrag[np * 2 + 1][1] = r4[3];
                }
#pragma unroll
                for (int mt = 0; mt < 2; mt++)
#pragma unroll
                    for (int nt = 0; nt < 8; nt++)
                        mma16816(acc[mt][nt], afrag[mt], bfrag[nt]);
            }
        }
    }

#pragma unroll
    for (int mt = 0; mt < 2; mt++) {
#pragma unroll
        for (int nt = 0; nt < 8; nt++) {
            int m = m0 + wm * 32 + mt * 16 + (lane >> 2);
            int nl = wn * 64 + nt * 8 + (lane & 3) * 2;
            float2 o0, o1;
            o0.x = acc[mt][nt][0] + sbias[nl];
            o0.y = acc[mt][nt][1] + sbias[nl + 1];
            o1.x = acc[mt][nt][2] + sbias[nl];
            o1.y = acc[mt][nt][3] + sbias[nl + 1];
            *(float2*)&out[(size_t)m * Hdim + n0 + nl] = o0;
            *(float2*)&out[(size_t)(m + 8) * Hdim + n0 + nl] = o1;
        }
    }
}

// ============================================================================
// Fused dual-layer recurrence. 128 CTAs x 512 threads (16 warps = 4/SMSP).
// Cohort A (0..63): warps 0-7 rec0, warps 8-15 xp2 (role split keeps acc=32
//   regs/thread). 8 phases x 128-k chunks, 2x32KB stage bufs (256B rows).
//   W for both GEMMs in SMEM (128KB).
// Cohort B (64..127): rec1, 16 warps each own a k16-tile per phase, 4 phases
//   x 256-k, W frags in registers, triple-buffered 64KB stages, gated on
//   g_stepA.
// ============================================================================
#define RNN_SMEM_BYTES 196608
// cohort A layout
#define A_WR_H   0          /* rec W hi 32K, lo at +32768 */
#define A_WX_H   65536      /* xp  W hi 32K, lo at +32768 */
#define A_S0b    131072     /* stage buf 0: hi 16K + lo 16K */
#define A_S1b    163840     /* stage buf 1 */
// cohort B layout
#define B_S0     0
#define B_S1     65536
#define B_S2     131072     /* also temp W staging during init */
#define B_WT_H   131072
#define B_WT_L   163840

// ---- cohort A staging: chunk c = 128 k-values, rows = b (256B), hi+lo ------
static __device__ __forceinline__ void stage_hA128(
    const __nv_bfloat16* __restrict__ hh, const __nv_bfloat16* __restrict__ hl,
    int c, char* dst, int tid)
{
#pragma unroll
    for (int r = 0; r < 2; r++) {
        int idx = r * 512 + tid;              // 0..1023
        int b = idx >> 4;                     // 0..63
        int g = idx & 15;                     // granule within 256B row
        int ph = (g & 8) | ((g ^ (b & 7)) & 7);
        uint32_t d = smem_u32(dst + b * 256 + ph * 16);
        const __nv_bfloat16* s = hh + b * Hdim + c * 128 + g * 8;
        asm volatile("cp.async.cg.shared.global [%0], [%1], 16;" ::"r"(d), "l"(s));
        const __nv_bfloat16* s2 = hl + b * Hdim + c * 128 + g * 8;
        asm volatile("cp.async.cg.shared.global [%0], [%1], 16;"
                     ::"r"(d + 16384), "l"(s2));
    }
}

// ---- cohort B staging: chunk kc = 256 k-values, rows = b (512B), hi+lo -----
static __device__ __forceinline__ void stage_hB256(
    const __nv_bfloat16* __restrict__ hh, const __nv_bfloat16* __restrict__ hl,
    int kc, char* dst, int tid)
{
#pragma unroll
    for (int r = 0; r < 4; r++) {
        int idx = r * 512 + tid;
        int b = idx >> 5;
        int lg = idx & 31;
        uint32_t d = smem_u32(dst + b * 512 + ((lg ^ (b & 7)) << 4));
        const __nv_bfloat16* s = hh + b * Hdim + kc * 256 + lg * 8;
        asm volatile("cp.async.cg.shared.global [%0], [%1], 16;" ::"r"(d), "l"(s));
        const __nv_bfloat16* s2 = hl + b * Hdim + kc * 256 + lg * 8;
        asm volatile("cp.async.cg.shared.global [%0], [%1], 16;"
                     ::"r"(d + 32768), "l"(s2));
    }
}

__global__ void __launch_bounds__(512) rnn_fused_kernel(
    const float* __restrict__ xp0, const float* __restrict__ Whh0,
    const float* __restrict__ Wih1, const float* __restrict__ bi1,
    const float* __restrict__ bh1, const float* __restrict__ Whh1,
    float* __restrict__ xp2)
{
    extern __shared__ __align__(1024) char smraw[];
    const int tid = threadIdx.x;
    const int bid = blockIdx.x;
    const int wid = tid >> 5;
    const int lane = tid & 31;

    if (bid == 0 && tid == 0)
        asm volatile("st.relaxed.gpu.global.u32 [%0], %1;"
                     :: "l"(&g_stepA), "r"(0u) : "memory");

    // ldmatrix lane mappings
    const int asub = lane >> 3;
    const int arow = (asub & 1) * 8 + (lane & 7);
    const int ack = asub >> 1;
    const int brow = ((lane >> 4) & 1) * 8 + (lane & 7);
    const int bck = (lane >> 3) & 1;
    // epilogue: 2 outputs per thread
    const int eb = tid >> 3;            // batch 0..63
    const int ej = (tid & 7) * 2;       // j within 16

    if (bid < 64) {
        // ==================== Cohort A ====================
        const int j0 = bid * 16;
        const int wg = wid >> 3;        // 0 = rec0, 1 = xp2
        const int wt = wid & 7;         // tile slot within phase
        float* p_rec = (float*)(smraw + A_S0b);
        float* p_xp  = (float*)(smraw + A_S1b);

        // W: rec0 -> A_WR, xp2 (Wih1) -> A_WX; hi/lo swizzled 2048B rows
        for (int i = tid; i < 8192; i += 512) {
            int row = i >> 8;                  // 0..31
            int col4 = i & 255;
            bool isrec = row < 16;
            int r = row & 15;
            const float* src = isrec
                ? &Whh0[(size_t)(j0 + r) * Hdim + col4 * 4]
                : &Wih1[(size_t)(j0 + r) * Hdim + col4 * 4];
            uint2 hi, lo;
            split_bf16(*(const float4*)src, hi, lo);
            int g = col4 >> 1;
            int off = r * 2048 + ((g ^ (r & 7)) << 4) + (col4 & 1) * 8;
            int base = isrec ? A_WR_H : A_WX_H;
            *(uint2*)(smraw + base + off) = hi;
            *(uint2*)(smraw + base + 32768 + off) = lo;
        }
        if (tid < 64) {
            uint4 z = make_uint4(0, 0, 0, 0);
            *(uint4*)&g_hh1[0][(size_t)tid * Hdim + j0] = z;
            *(uint4*)&g_hh1[0][(size_t)tid * Hdim + j0 + 8] = z;
            *(uint4*)&g_hl1[0][(size_t)tid * Hdim + j0] = z;
            *(uint4*)&g_hl1[0][(size_t)tid * Hdim + j0 + 8] = z;
        }
        float bias2[2];
        bias2[0] = bi1[j0 + ej] + bh1[j0 + ej];
        bias2[1] = bi1[j0 + ej + 1] + bh1[j0 + ej + 1];

        const uint32_t wbh = smem_u32(smraw + (wg ? A_WX_H : A_WR_H));
        const uint32_t wbl = wbh + 32768;

        grid_sync_p(&g_barG_cnt, &g_barG_gen, 128);

#pragma unroll 1
        for (int s = 0; s <= Sdim; s++) {
            const __nv_bfloat16* hh_in = g_hh1[s & 1];
            const __nv_bfloat16* hl_in = g_hl1[s & 1];
            __nv_bfloat16* hh_out = g_hh1[(s + 1) & 1];
            __nv_bfloat16* hl_out = g_hl1[(s + 1) & 1];

            int tt = (s < Sdim) ? s : Sdim - 1;
            float2 xpv = *(const float2*)&xp0[((size_t)eb * Sdim + tt) * Hdim
                                              + j0 + ej];

            float acc[4][2][4];
#pragma unroll
            for (int mt = 0; mt < 4; mt++)
#pragma unroll
                for (int nt = 0; nt < 2; nt++)
#pragma unroll
                    for (int i = 0; i < 4; i++) acc[mt][nt][i] = 0.0f;

            stage_hA128(hh_in, hl_in, 0, smraw + A_S0b, tid);
            asm volatile("cp.async.commit_group;");
            stage_hA128(hh_in, hl_in, 1, smraw + A_S1b, tid);
            asm volatile("cp.async.commit_group;");

#pragma unroll
            for (int c = 0; c < 8; c++) {
                if (c < 7) asm volatile("cp.async.wait_group 1;");
                else       asm volatile("cp.async.wait_group 0;");
                __syncthreads();

                const uint32_t shb = smem_u32(smraw + ((c & 1) ? A_S1b : A_S0b));
                const uint32_t slb = shb + 16384;

                // A fragments (4 m-tiles, hi + lo) for this warp's k16 tile
                uint32_t ah[4][4], al[4][4];
                int gA = wt * 2 + ack;
#pragma unroll
                for (int mt = 0; mt < 4; mt++) {
                    int row = mt * 16 + arow;
                    uint32_t ph = (uint32_t)((gA & 8) | ((gA ^ (row & 7)) & 7)) << 4;
                    ldsm_x4(shb + row * 256 + ph, ah[mt]);
                    ldsm_x4(slb + row * 256 + ph, al[mt]);
                }
                // W fragment for role GEMM, k16 index = c*8 + wt
                int gB = (c * 8 + wt) * 2 + bck;
                uint32_t bsw = (uint32_t)((gB ^ (brow & 7)) << 4);
                uint32_t wh[4], wl[4];
                ldsm_x4(wbh + brow * 2048 + bsw, wh);
                ldsm_x4(wbl + brow * 2048 + bsw, wl);

#pragma unroll
                for (int mt = 0; mt < 4; mt++) {
                    mma16816(acc[mt][0], ah[mt], &wh[0]);
                    mma16816(acc[mt][1], ah[mt], &wh[2]);
                    mma16816(acc[mt][0], ah[mt], &wl[0]);
                    mma16816(acc[mt][1], ah[mt], &wl[2]);
                    mma16816(acc[mt][0], al[mt], &wh[0]);
                    mma16816(acc[mt][1], al[mt], &wh[2]);
                }
                if (c < 6) {
                    __syncthreads();     // all warps done reading this buffer
                    stage_hA128(hh_in, hl_in, c + 2,
                                smraw + ((c & 1) ? A_S1b : A_S0b), tid);
                    asm volatile("cp.async.commit_group;");
                }
            }
            __syncthreads();   // phase-7 reads (S1) complete before overwrites

            // partials: rec warps -> p_rec[wt][1024], xp warps -> p_xp[wt][1024]
            {
                float* pdst = wg ? p_xp : p_rec;
#pragma unroll
                for (int mt = 0; mt < 4; mt++)
#pragma unroll
                    for (int nt = 0; nt < 2; nt++) {
                        int b = mt * 16 + (lane >> 2);
                        int j = nt * 8 + (lane & 3) * 2;
                        *(float2*)&pdst[wt * 1024 + b * 16 + j] =
                            make_float2(acc[mt][nt][0], acc[mt][nt][1]);
                        *(float2*)&pdst[wt * 1024 + (b + 8) * 16 + j] =
                            make_float2(acc[mt][nt][2], acc[mt][nt][3]);
                    }
            }
            __syncthreads();

            {
                int o = tid * 2;
                float2 sr = *(const float2*)&p_rec[o];
                float2 sx = *(const float2*)&p_xp[o];
#pragma unroll
                for (int w = 1; w < 8; w++) {
                    float2 q = *(const float2*)&p_rec[w * 1024 + o];
                    sr.x += q.x; sr.y += q.y;
                    float2 q2 = *(const float2*)&p_xp[w * 1024 + o];
                    sx.x += q2.x; sx.y += q2.y;
                }
                if (s < Sdim) {
                    float v0 = tanhf(sr.x + xpv.x);
                    float v1 = tanhf(sr.y + xpv.y);
                    unsigned hi, lo;
                    split2_bf16(v0, v1, hi, lo);
                    size_t ho = (size_t)eb * Hdim + j0 + ej;
                    *(unsigned*)&hh_out[ho] = hi;
                    *(unsigned*)&hl_out[ho] = lo;
                }
                if (s >= 1) {
                    float2 o2;
                    o2.x = sx.x + bias2[0];
                    o2.y = sx.y + bias2[1];
                    *(float2*)&xp2[((size_t)(s - 1) * Bdim + eb) * Hdim + j0 + ej]
                        = o2;
                }
            }
            __syncthreads();
            if (s >= 1 && tid == 0)
                asm volatile("red.release.gpu.global.add.u32 [%0], 1;"
                             :: "l"(&g_stepA) : "memory");
            if (s < Sdim) grid_sync_p(&g_barA_cnt, &g_barA_gen, 64);
        }
    } else {
        // ==================== Cohort B ====================
        const int j0 = (bid - 64) * 16;
        float* p_s = (float*)(smraw + B_S0);   // 16 warps x 1024 floats = 64KB

        // rec1 W -> temp SMEM (buf2 region), then to registers
        for (int i = tid; i < 4096; i += 512) {
            int j = i >> 8;
            int col4 = i & 255;
            uint2 hi, lo;
            split_bf16(*(const float4*)&Whh1[(size_t)(j0 + j) * Hdim + col4 * 4],
                       hi, lo);
            int g = col4 >> 1;
            int off = j * 2048 + ((g ^ (j & 7)) << 4) + (col4 & 1) * 8;
            *(uint2*)(smraw + B_WT_H + off) = hi;
            *(uint2*)(smraw + B_WT_L + off) = lo;
        }
        if (tid < 64) {
            uint4 z = make_uint4(0, 0, 0, 0);
            *(uint4*)&g_hh2[0][(size_t)tid * Hdim + j0] = z;
            *(uint4*)&g_hh2[0][(size_t)tid * Hdim + j0 + 8] = z;
            *(uint4*)&g_hl2[0][(size_t)tid * Hdim + j0] = z;
            *(uint4*)&g_hl2[0][(size_t)tid * Hdim + j0 + 8] = z;
        }
        __syncthreads();

        // preload all rec1 W fragments into registers (4 k16 tiles per warp)
        uint32_t wBh[4][4], wBl[4][4];
#pragma unroll
        for (int c = 0; c < 4; c++) {
            int gB = (c * 16 + wid) * 2 + bck;
            uint32_t sw = (uint32_t)((gB ^ (brow & 7)) << 4);
            ldsm_x4(smem_u32(smraw + B_WT_H) + brow * 2048 + sw, wBh[c]);
            ldsm_x4(smem_u32(smraw + B_WT_L) + brow * 2048 + sw, wBl[c]);
        }
        grid_sync_p(&g_barG_cnt, &g_barG_gen, 128);

#pragma unroll 1
        for (int t = 0; t < Sdim; t++) {
            // gate: xp2[t] published by cohort A (count = 64*(t+1))
            if (tid == 0) {
                unsigned tgt = 64u * (unsigned)(t + 1);
                unsigned cur;
                do {
                    asm volatile("ld.acquire.gpu.global.u32 %0, [%1];"
                                 : "=r"(cur) : "l"(&g_stepA) : "memory");
                } while (cur < tgt);
            }
            __syncthreads();

            const __nv_bfloat16* hh_in = g_hh2[t & 1];
            const __nv_bfloat16* hl_in = g_hl2[t & 1];
            __nv_bfloat16* hh_out = g_hh2[(t + 1) & 1];
            __nv_bfloat16* hl_out = g_hl2[(t + 1) & 1];

            float2 xpv = *(const float2*)&xp2[((size_t)t * Bdim + eb) * Hdim
                                              + j0 + ej];

            float acc[4][2][4];
#pragma unroll
            for (int mt = 0; mt < 4; mt++)
#pragma unroll
                for (int nt = 0; nt < 2; nt++)
#pragma unroll
                    for (int i = 0; i < 4; i++) acc[mt][nt][i] = 0.0f;

            stage_hB256(hh_in, hl_in, 0, smraw + B_S0, tid);
            asm volatile("cp.async.commit_group;");
            stage_hB256(hh_in, hl_in, 1, smraw + B_S1, tid);
            asm volatile("cp.async.commit_group;");

#pragma unroll
            for (int c = 0; c < 4; c++) {
                if (c < 3) asm volatile("cp.async.wait_group 1;");
                else       asm volatile("cp.async.wait_group 0;");
                __syncthreads();

                const int bufi = c % 3;
                const uint32_t shb = smem_u32(smraw + (size_t)bufi * 65536);
                const uint32_t slb = shb + 32768;

                // warp's k16 tile within this 256-k chunk
                uint32_t ah[4][4], al[4][4];
                int gA = wid * 2 + ack;
#pragma unroll
                for (int mt = 0; mt < 4; mt++) {
                    int row = mt * 16 + arow;
                    uint32_t sw = (uint32_t)((gA ^ (row & 7)) << 4);
                    ldsm_x4(shb + row * 512 + sw, ah[mt]);
                    ldsm_x4(slb + row * 512 + sw, al[mt]);
                }
#pragma unroll
                for (int mt = 0; mt < 4; mt++) {
                    mma16816(acc[mt][0], ah[mt], &wBh[c][0]);
                    mma16816(acc[mt][1], ah[mt], &wBh[c][2]);
                    mma16816(acc[mt][0], ah[mt], &wBl[c][0]);
                    mma16816(acc[mt][1], ah[mt], &wBl[c][2]);
                    mma16816(acc[mt][0], al[mt], &wBh[c][0]);
                    mma16816(acc[mt][1], al[mt], &wBh[c][2]);
                }
                if (c + 2 < 4) {
                    // triple buffer: target buf (c+2)%3 was last read in
                    // phase c-1; top-of-phase sync already ordered those reads.
                    stage_hB256(hh_in, hl_in, c + 2,
                                smraw + (size_t)((c + 2) % 3) * 65536, tid);
                    asm volatile("cp.async.commit_group;");
                }
            }
            __syncthreads();   // phase-3 reads of buf0 done before p_s writes

#pragma unroll
            for (int mt = 0; mt < 4; mt++)
#pragma unroll
                for (int nt = 0; nt < 2; nt++) {
                    int b = mt * 16 + (lane >> 2);
                    int j = nt * 8 + (lane & 3) * 2;
                    *(float2*)&p_s[wid * 1024 + b * 16 + j] =
                        make_float2(acc[mt][nt][0], acc[mt][nt][1]);
                    *(float2*)&p_s[wid * 1024 + (b + 8) * 16 + j] =
                        make_float2(acc[mt][nt][2], acc[mt][nt][3]);
                }
            __syncthreads();

            {
                int o = tid * 2;
                float2 s = *(const float2*)&p_s[o];
#pragma unroll
                for (int w = 1; w < 16; w++) {
                    float2 q = *(const float2*)&p_s[w * 1024 + o];
                    s.x += q.x; s.y += q.y;
                }
                float v0 = tanhf(s.x + xpv.x);
                float v1 = tanhf(s.y + xpv.y);
                unsigned hi, lo;
                split2_bf16(v0, v1, hi, lo);
                size_t ho = (size_t)eb * Hdim + j0 + ej;
                *(unsigned*)&hh_out[ho] = hi;
                *(unsigned*)&hl_out[ho] = lo;
            }
            grid_sync_p(&g_barB_cnt, &g_barB_gen, 64);
        }
    }
}

// ============================================================================
// Final FC + sigmoid: h_last = g_hh2[0] + g_hl2[0]  ((511+1)&1 = 0)
// ============================================================================
__global__ void fc_kernel(const __nv_bfloat16* __restrict__ hh,
                          const __nv_bfloat16* __restrict__ hl,
                          const float* __restrict__ fcw,
                          const float* __restrict__ fcb,
                          float* __restrict__ out)
{
    __shared__ float red[8];
    int b = blockIdx.x, tid = threadIdx.x;
    float s = 0.0f;
    for (int k = tid; k < Hdim; k += 256) {
        float h = __bfloat162float(hh[b * Hdim + k]) +
                  __bfloat162float(hl[b * Hdim + k]);
        s += h * fcw[k];
    }
#pragma unroll
    for (int o = 16; o; o >>= 1) s += __shfl_xor_sync(0xFFFFFFFFu, s, o);
    if ((tid & 31) == 0) red[tid >> 5] = s;
    __syncthreads();
    if (tid == 0) {
        float tot = 0.0f;
#pragma unroll
        for (int i = 0; i < 8; i++) tot += red[i];
        float logit = tot + fcb[0];
        out[b] = 1.0f / (1.0f + expf(-logit));
    }
}

// ============================================================================
extern "C" void kernel_launch(void* const* d_in, const int* in_sizes, int n_in,
                              void* d_out, int out_size)
{
    const float* x     = (const float*)d_in[0];
    const float* W_ih0 = (const float*)d_in[1];
    const float* W_hh0 = (const float*)d_in[2];
    const float* b_ih0 = (const float*)d_in[3];
    const float* b_hh0 = (const float*)d_in[4];
    const float* W_ih1 = (const float*)d_in[5];
    const float* W_hh1 = (const float*)d_in[6];
    const float* b_ih1 = (const float*)d_in[7];
    const float* b_hh1 = (const float*)d_in[8];
    const float* fc_w  = (const float*)d_in[9];
    const float* fc_b  = (const float*)d_in[10];
    float* out = (float*)d_out;

    float *xp, *xp2;
    __nv_bfloat16 *hh2, *hl2;
    cudaGetSymbolAddress((void**)&xp, g_xp);
    cudaGetSymbolAddress((void**)&xp2, g_xp2);
    cudaGetSymbolAddress((void**)&hh2, g_hh2);
    cudaGetSymbolAddress((void**)&hl2, g_hl2);

    cudaFuncSetAttribute(rnn_fused_kernel,
                         cudaFuncAttributeMaxDynamicSharedMemorySize,
                         RNN_SMEM_BYTES);
    cudaFuncSetAttribute(xproj_mma_kernel<Fdim>,
                         cudaFuncAttributeMaxDynamicSharedMemorySize, XP_SMEM);

    dim3 xgrid(8, 256);
    // layer-0 xp: rows m = b*S + t -> xp[(b*S+t)*H + j]
    xproj_mma_kernel<Fdim><<<xgrid, 256, XP_SMEM>>>(x, W_ih0, b_ih0, b_hh0, xp);
    // fused dual-layer recurrence (A: rec0 + xp2 with role-split warps; B: rec1)
    rnn_fused_kernel<<<128, 512, RNN_SMEM_BYTES>>>(
        xp, W_hh0, W_ih1, b_ih1, b_hh1, W_hh1, xp2);
    // head: final h2 in slot 0
    fc_kernel<<<64, 256>>>(hh2, hl2, fc_w, fc_b, out);
}

// round 14
// speedup vs baseline: 1.1125x; 1.1125x over previous
#include <cuda_runtime.h>
#include <cuda_bf16.h>
#include <math.h>
#include <stdint.h>

#define Bdim 64
#define Sdim 512
#define Fdim 512
#define Hdim 1024

// ---------------- scratch (static device globals; no runtime allocation) ----
__device__ float g_xp[(size_t)Bdim * Sdim * Hdim];    // xp layer 0 (from x)
__device__ float g_xp2[(size_t)Bdim * Sdim * Hdim];   // xp layer 1 [t][b][H]
__device__ __nv_bfloat16 g_hh1[2][Bdim * Hdim];       // layer-0 hidden hi, [b][k]
__device__ __nv_bfloat16 g_hl1[2][Bdim * Hdim];       // layer-0 hidden lo
__device__ __nv_bfloat16 g_hh2[2][Bdim * Hdim];       // layer-1 hidden hi
__device__ __nv_bfloat16 g_hl2[2][Bdim * Hdim];       // layer-1 hidden lo
__device__ unsigned g_barG_cnt = 0; __device__ unsigned g_barG_gen = 0;
__device__ unsigned g_barA_cnt = 0; __device__ unsigned g_barA_gen = 0;
__device__ unsigned g_barB_cnt = 0; __device__ unsigned g_barB_gen = 0;
__device__ unsigned g_stepA = 0;    // A publications: 64 per completed xp2 step

static __device__ __forceinline__ unsigned smem_u32(const void* p) {
    return (unsigned)__cvta_generic_to_shared(p);
}

// ---------------- cohort barrier: scoped release/acquire --------------------
static __device__ __forceinline__ void grid_sync_p(unsigned* cnt, unsigned* gen,
                                                   int nblocks) {
    __syncthreads();
    if (threadIdx.x == 0) {
        unsigned g;
        asm volatile("ld.relaxed.gpu.global.u32 %0, [%1];" : "=r"(g) : "l"(gen));
        unsigned old;
        asm volatile("atom.acq_rel.gpu.global.add.u32 %0, [%1], 1;"
                     : "=r"(old) : "l"(cnt) : "memory");
        if (old == (unsigned)(nblocks - 1)) {
            asm volatile("st.relaxed.gpu.global.u32 [%0], %1;"
                         :: "l"(cnt), "r"(0u) : "memory");
            asm volatile("st.release.gpu.global.u32 [%0], %1;"
                         :: "l"(gen), "r"(g + 1) : "memory");
        } else {
            unsigned cur;
            do {
                asm volatile("ld.acquire.gpu.global.u32 %0, [%1];"
                             : "=r"(cur) : "l"(gen) : "memory");
            } while (cur == g);
        }
    }
    __syncthreads();
}

// ---------------- mma.sync helpers ------------------------------------------
static __device__ __forceinline__ void ldsm_x4(uint32_t addr, uint32_t* r) {
    asm volatile("ldmatrix.sync.aligned.m8n8.x4.shared.b16 {%0,%1,%2,%3}, [%4];"
                 : "=r"(r[0]), "=r"(r[1]), "=r"(r[2]), "=r"(r[3]) : "r"(addr));
}
static __device__ __forceinline__ void mma16816(float* c, const uint32_t* a,
                                                const uint32_t* b) {
    asm volatile("mma.sync.aligned.m16n8k16.row.col.f32.bf16.bf16.f32 "
                 "{%0,%1,%2,%3}, {%4,%5,%6,%7}, {%8,%9}, {%0,%1,%2,%3};"
                 : "+f"(c[0]), "+f"(c[1]), "+f"(c[2]), "+f"(c[3])
                 : "r"(a[0]), "r"(a[1]), "r"(a[2]), "r"(a[3]),
                   "r"(b[0]), "r"(b[1]));
}
static __device__ __forceinline__ void split_bf16(float4 v, uint2& hi, uint2& lo) {
    __nv_bfloat162 h01 = __floats2bfloat162_rn(v.x, v.y);
    __nv_bfloat162 h23 = __floats2bfloat162_rn(v.z, v.w);
    __nv_bfloat162 l01 = __floats2bfloat162_rn(v.x - __low2float(h01),
                                               v.y - __high2float(h01));
    __nv_bfloat162 l23 = __floats2bfloat162_rn(v.z - __low2float(h23),
                                               v.w - __high2float(h23));
    hi = make_uint2(*(unsigned*)&h01, *(unsigned*)&h23);
    lo = make_uint2(*(unsigned*)&l01, *(unsigned*)&l23);
}
static __device__ __forceinline__ void split2_bf16(float v0, float v1,
                                                   unsigned& hi, unsigned& lo) {
    __nv_bfloat162 h = __floats2bfloat162_rn(v0, v1);
    __nv_bfloat162 l = __floats2bfloat162_rn(v0 - __low2float(h),
                                             v1 - __high2float(h));
    hi = *(unsigned*)&h;
    lo = *(unsigned*)&l;
}

// ============================================================================
// xproj kernel for layer-0 xp (proven R7 body): out = A@Wt^T + ba + bb
// ============================================================================
#define SW128(o) ((o) ^ (((o) >> 3) & 0x70))
#define XP_OFF_BIAS 0
#define XP_OFF_AH   1024
#define XP_OFF_AL   (XP_OFF_AH + 16384)
#define XP_OFF_BH   (XP_OFF_AL + 16384)
#define XP_OFF_BL   (XP_OFF_BH + 16384)
#define XP_SMEM     (XP_OFF_BL + 16384)

static __device__ __forceinline__ uint32_t lm_addr(uint32_t base, int r, int ck) {
    return base + r * 128 + ((ck ^ (r & 7)) << 4);
}

template <int K>
__global__ void __launch_bounds__(256, 2) xproj_mma_kernel(
    const float* __restrict__ A, const float* __restrict__ Wt,
    const float* __restrict__ ba, const float* __restrict__ bb,
    float* __restrict__ out)
{
    extern __shared__ __align__(1024) char xsm[];
    const uint32_t sb = smem_u32(xsm);
    const int tid = threadIdx.x;
    const int wid = tid >> 5;
    const int lane = tid & 31;
    const int wm = wid & 3;
    const int wn = wid >> 2;
    const int m0 = blockIdx.y * 128;
    const int n0 = blockIdx.x * 128;

    float* sbias = (float*)(xsm + XP_OFF_BIAS);
    if (tid < 128) sbias[tid] = ba[n0 + tid] + bb[n0 + tid];

    float acc[2][8][4];
#pragma unroll
    for (int mt = 0; mt < 2; mt++)
#pragma unroll
        for (int nt = 0; nt < 8; nt++)
#pragma unroll
            for (int i = 0; i < 4; i++) acc[mt][nt][i] = 0.0f;

    const int NKT = K / 64;
#pragma unroll 1
    for (int kt = 0; kt < NKT; kt++) {
        __syncthreads();
        const float* Asrc = A + (size_t)m0 * K + kt * 64;
        const float* Bsrc = Wt + (size_t)n0 * K + kt * 64;
#pragma unroll
        for (int r = 0; r < 8; r++) {
            int idx = r * 256 + tid;
            int row = idx >> 4;
            int c4 = idx & 15;
            int sw = SW128(row * 128 + c4 * 8);
            uint2 hi, lo;
            split_bf16(*(const float4*)&Asrc[(size_t)row * K + c4 * 4], hi, lo);
            *(uint2*)(xsm + XP_OFF_AH + sw) = hi;
            *(uint2*)(xsm + XP_OFF_AL + sw) = lo;
            split_bf16(*(const float4*)&Bsrc[(size_t)row * K + c4 * 4], hi, lo);
            *(uint2*)(xsm + XP_OFF_BH + sw) = hi;
            *(uint2*)(xsm + XP_OFF_BL + sw) = lo;
        }
        __syncthreads();

        const int asub = lane >> 3;
        const int arow = (asub & 1) * 8 + (lane & 7);
        const int ack = asub >> 1;
        const int brow = ((lane >> 4) & 1) * 8 + (lane & 7);
        const int bck = (lane >> 3) & 1;

#pragma unroll
        for (int p = 0; p < 3; p++) {
            uint32_t aBase = sb + ((p == 2) ? XP_OFF_AL : XP_OFF_AH);
            uint32_t bBase = sb + ((p == 1) ? XP_OFF_BL : XP_OFF_BH);
#pragma unroll
            for (int kk = 0; kk < 4; kk++) {
                uint32_t afrag[2][4], bfrag[8][2];
#pragma unroll
                for (int mt = 0; mt < 2; mt++)
                    ldsm_x4(lm_addr(aBase, wm * 32 + mt * 16 + arow, kk * 2 + ack),
                            afrag[mt]);
#pragma unroll
                for (int np = 0; np < 4; np++) {
                    uint32_t r4[4];
                    ldsm_x4(lm_addr(bBase, wn * 64 + np * 16 + brow, kk * 2 + bck), r4);
                    bfrag[np * 2][0] = r4[0]; bfrag[np * 2][1] = r4[1];
                    bfrag[np * 2 + 1][0] = r4[2]; bfrag[np * 2 + 1][1] = r4[3];
                }
#pragma unroll
                for (int mt = 0; mt < 2; mt++)
#pragma unroll
                    for (int nt = 0; nt < 8; nt++)
                        mma16816(acc[mt][nt], afrag[mt], bfrag[nt]);
            }
        }
    }

#pragma unroll
    for (int mt = 0; mt < 2; mt++) {
#pragma unroll
        for (int nt = 0; nt < 8; nt++) {
            int m = m0 + wm * 32 + mt * 16 + (lane >> 2);
            int nl = wn * 64 + nt * 8 + (lane & 3) * 2;
            float2 o0, o1;
            o0.x = acc[mt][nt][0] + sbias[nl];
            o0.y = acc[mt][nt][1] + sbias[nl + 1];
            o1.x = acc[mt][nt][2] + sbias[nl];
            o1.y = acc[mt][nt][3] + sbias[nl + 1];
            *(float2*)&out[(size_t)m * Hdim + n0 + nl] = o0;
            *(float2*)&out[(size_t)(m + 8) * Hdim + n0 + nl] = o1;
        }
    }
}

// ============================================================================
// Fused dual-layer recurrence. 128 CTAs x 256 threads.
// Both cohorts: 8 phases x 128-k chunks, FOUR 32KB stage buffers, prefetch
// depth 3, ONE syncthreads per phase (restage target = buffer read 2 phases
// ago, ordered by the top-of-phase sync). rec W fragments in registers
// (8 k16 tiles = 64 regs). A also runs xp2 (W in SMEM, 64KB).
// ============================================================================
#define RNN_SMEM_BYTES 196608
// cohort A: xp W at [0,64K); 4 stage bufs at 64K + i*32K; temp rec W in bufs
#define A_WX_H   0
#define A_WX_L   32768
#define A_BUF(i) (65536 + (i) * 32768)
// cohort B: 4 stage bufs at i*32K; temp rec W at 128K..192K
#define B_BUF(i) ((i) * 32768)
#define B_WT_H   131072
#define B_WT_L   163840

// stage one 128-k chunk of h (hi+lo) into a 32KB buffer.
// layout: 64 b-rows x 256B, granule swizzle ph = (g&8)|((g^(b&7))&7).
static __device__ __forceinline__ void stage_h128(
    const __nv_bfloat16* __restrict__ hh, const __nv_bfloat16* __restrict__ hl,
    int c, char* dst, int tid)
{
#pragma unroll
    for (int r = 0; r < 4; r++) {
        int idx = r * 256 + tid;              // 0..1023
        int b = idx >> 4;                     // 0..63
        int g = idx & 15;                     // granule within 256B row
        int ph = (g & 8) | ((g ^ (b & 7)) & 7);
        uint32_t d = smem_u32(dst + b * 256 + ph * 16);
        const __nv_bfloat16* s = hh + b * Hdim + c * 128 + g * 8;
        asm volatile("cp.async.cg.shared.global [%0], [%1], 16;" ::"r"(d), "l"(s));
        const __nv_bfloat16* s2 = hl + b * Hdim + c * 128 + g * 8;
        asm volatile("cp.async.cg.shared.global [%0], [%1], 16;"
                     ::"r"(d + 16384), "l"(s2));
    }
}

__global__ void __launch_bounds__(256) rnn_fused_kernel(
    const float* __restrict__ xp0, const float* __restrict__ Whh0,
    const float* __restrict__ Wih1, const float* __restrict__ bi1,
    const float* __restrict__ bh1, const float* __restrict__ Whh1,
    float* __restrict__ xp2)
{
    extern __shared__ __align__(1024) char smraw[];
    const int tid = threadIdx.x;
    const int bid = blockIdx.x;
    const int wid = tid >> 5;
    const int lane = tid & 31;

    if (bid == 0 && tid == 0)
        asm volatile("st.relaxed.gpu.global.u32 [%0], %1;"
                     :: "l"(&g_stepA), "r"(0u) : "memory");

    // ldmatrix lane mappings
    const int asub = lane >> 3;
    const int arow = (asub & 1) * 8 + (lane & 7);
    const int ack = asub >> 1;
    const int brow = ((lane >> 4) & 1) * 8 + (lane & 7);
    const int bck = (lane >> 3) & 1;
    // epilogue: 4 outputs per thread
    const int eb = tid >> 2;
    const int ej = (tid & 3) * 4;

    if (bid < 64) {
        // ==================== Cohort A: rec0 + xp2 ====================
        const int j0 = bid * 16;
        float* p_rec = (float*)(smraw + A_BUF(0));   // partials alias bufs 0/1
        float* p_xp  = (float*)(smraw + A_BUF(1));

        // W staging: xp W (Wih1) permanent at A_WX; rec W (Whh0) temp in bufs
        for (int i = tid; i < 8192; i += 256) {
            int row = i >> 8;                  // 0..31: 0-15 rec, 16-31 xp
            int col4 = i & 255;
            bool isrec = row < 16;
            int r = row & 15;
            const float* src = isrec
                ? &Whh0[(size_t)(j0 + r) * Hdim + col4 * 4]
                : &Wih1[(size_t)(j0 + r) * Hdim + col4 * 4];
            uint2 hi, lo;
            split_bf16(*(const float4*)src, hi, lo);
            int g = col4 >> 1;
            int off = r * 2048 + ((g ^ (r & 7)) << 4) + (col4 & 1) * 8;
            if (isrec) {
                *(uint2*)(smraw + A_BUF(0) + off) = hi;
                *(uint2*)(smraw + A_BUF(1) + off) = lo;
            } else {
                *(uint2*)(smraw + A_WX_H + off) = hi;
                *(uint2*)(smraw + A_WX_L + off) = lo;
            }
        }
        if (tid < 64) {
            uint4 z = make_uint4(0, 0, 0, 0);
            *(uint4*)&g_hh1[0][(size_t)tid * Hdim + j0] = z;
            *(uint4*)&g_hh1[0][(size_t)tid * Hdim + j0 + 8] = z;
            *(uint4*)&g_hl1[0][(size_t)tid * Hdim + j0] = z;
            *(uint4*)&g_hl1[0][(size_t)tid * Hdim + j0 + 8] = z;
        }
        float bias2[4];
#pragma unroll
        for (int i = 0; i < 4; i++)
            bias2[i] = bi1[j0 + ej + i] + bh1[j0 + ej + i];
        __syncthreads();

        // preload rec-W fragments into registers: tile c = k16 idx c*8+wid
        uint32_t wRh[8][4], wRl[8][4];
#pragma unroll
        for (int c = 0; c < 8; c++) {
            int gB = (c * 8 + wid) * 2 + bck;
            uint32_t sw = (uint32_t)((gB ^ (brow & 7)) << 4);
            ldsm_x4(smem_u32(smraw + A_BUF(0)) + brow * 2048 + sw, wRh[c]);
            ldsm_x4(smem_u32(smraw + A_BUF(1)) + brow * 2048 + sw, wRl[c]);
        }
        grid_sync_p(&g_barG_cnt, &g_barG_gen, 128);

#pragma unroll 1
        for (int s = 0; s <= Sdim; s++) {
            const __nv_bfloat16* hh_in = g_hh1[s & 1];
            const __nv_bfloat16* hl_in = g_hl1[s & 1];
            __nv_bfloat16* hh_out = g_hh1[(s + 1) & 1];
            __nv_bfloat16* hl_out = g_hl1[(s + 1) & 1];

            int tt = (s < Sdim) ? s : Sdim - 1;
            float4 xpv = *(const float4*)&xp0[((size_t)eb * Sdim + tt) * Hdim
                                              + j0 + ej];

            float accR[4][2][4], accX[4][2][4];
#pragma unroll
            for (int mt = 0; mt < 4; mt++)
#pragma unroll
                for (int nt = 0; nt < 2; nt++)
#pragma unroll
                    for (int i = 0; i < 4; i++) {
                        accR[mt][nt][i] = 0.0f;
                        accX[mt][nt][i] = 0.0f;
                    }

            stage_h128(hh_in, hl_in, 0, smraw + A_BUF(0), tid);
            asm volatile("cp.async.commit_group;");
            stage_h128(hh_in, hl_in, 1, smraw + A_BUF(1), tid);
            asm volatile("cp.async.commit_group;");
            stage_h128(hh_in, hl_in, 2, smraw + A_BUF(2), tid);
            asm volatile("cp.async.commit_group;");

#pragma unroll
            for (int c = 0; c < 8; c++) {
                if (c < 6)      asm volatile("cp.async.wait_group 2;");
                else if (c == 6) asm volatile("cp.async.wait_group 1;");
                else             asm volatile("cp.async.wait_group 0;");
                __syncthreads();   // chunk c visible; also orders phase c-1
                                   // reads of buf (c+3)&3 before its restage

                const uint32_t shb = smem_u32(smraw + A_BUF(c & 3));
                const uint32_t slb = shb + 16384;
                const uint32_t wxh = smem_u32(smraw + A_WX_H);
                const uint32_t wxl = smem_u32(smraw + A_WX_L);

                uint32_t ah[4][4], al[4][4];
                int gA = wid * 2 + ack;
#pragma unroll
                for (int mt = 0; mt < 4; mt++) {
                    int row = mt * 16 + arow;
                    uint32_t ph = (uint32_t)((gA & 8) | ((gA ^ (row & 7)) & 7)) << 4;
                    ldsm_x4(shb + row * 256 + ph, ah[mt]);
                    ldsm_x4(slb + row * 256 + ph, al[mt]);
                }
                int gB = (c * 8 + wid) * 2 + bck;
                uint32_t bsw = (uint32_t)((gB ^ (brow & 7)) << 4);
                uint32_t xh[4], xl[4];
                ldsm_x4(wxh + brow * 2048 + bsw, xh);
                ldsm_x4(wxl + brow * 2048 + bsw, xl);

#pragma unroll
                for (int mt = 0; mt < 4; mt++) {
                    mma16816(accR[mt][0], ah[mt], &wRh[c][0]);
                    mma16816(accR[mt][1], ah[mt], &wRh[c][2]);
                    mma16816(accR[mt][0], ah[mt], &wRl[c][0]);
                    mma16816(accR[mt][1], ah[mt], &wRl[c][2]);
                    mma16816(accR[mt][0], al[mt], &wRh[c][0]);
                    mma16816(accR[mt][1], al[mt], &wRh[c][2]);
                    mma16816(accX[mt][0], ah[mt], &xh[0]);
                    mma16816(accX[mt][1], ah[mt], &xh[2]);
                    mma16816(accX[mt][0], ah[mt], &xl[0]);
                    mma16816(accX[mt][1], ah[mt], &xl[2]);
                    mma16816(accX[mt][0], al[mt], &xh[0]);
                    mma16816(accX[mt][1], al[mt], &xh[2]);
                }
                if (c + 3 < 8) {
                    stage_h128(hh_in, hl_in, c + 3,
                               smraw + A_BUF((c + 3) & 3), tid);
                    asm volatile("cp.async.commit_group;");
                }
            }
            // all warps are past phase 7's sync -> bufs 0/1 free for partials
#pragma unroll
            for (int mt = 0; mt < 4; mt++)
#pragma unroll
                for (int nt = 0; nt < 2; nt++) {
                    int b = mt * 16 + (lane >> 2);
                    int j = nt * 8 + (lane & 3) * 2;
                    *(float2*)&p_rec[wid * 1024 + b * 16 + j] =
                        make_float2(accR[mt][nt][0], accR[mt][nt][1]);
                    *(float2*)&p_rec[wid * 1024 + (b + 8) * 16 + j] =
                        make_float2(accR[mt][nt][2], accR[mt][nt][3]);
                    *(float2*)&p_xp[wid * 1024 + b * 16 + j] =
                        make_float2(accX[mt][nt][0], accX[mt][nt][1]);
                    *(float2*)&p_xp[wid * 1024 + (b + 8) * 16 + j] =
                        make_float2(accX[mt][nt][2], accX[mt][nt][3]);
                }
            __syncthreads();

            {
                int o = tid * 4;
                // rec first: publish h1 ASAP (it gates the whole chip)
                float4 sr = *(const float4*)&p_rec[o];
#pragma unroll
                for (int w = 1; w < 8; w++) {
                    float4 q = *(const float4*)&p_rec[w * 1024 + o];
                    sr.x += q.x; sr.y += q.y; sr.z += q.z; sr.w += q.w;
                }
                if (s < Sdim) {
                    float v0 = tanhf(sr.x + xpv.x);
                    float v1 = tanhf(sr.y + xpv.y);
                    float v2 = tanhf(sr.z + xpv.z);
                    float v3 = tanhf(sr.w + xpv.w);
                    unsigned h01, l01, h23, l23;
                    split2_bf16(v0, v1, h01, l01);
                    split2_bf16(v2, v3, h23, l23);
                    size_t ho = (size_t)eb * Hdim + j0 + ej;
                    *(uint2*)&hh_out[ho] = make_uint2(h01, h23);
                    *(uint2*)&hl_out[ho] = make_uint2(l01, l23);
                }
                // xp2 second (only consumed by cohort B via g_stepA)
                float4 sx = *(const float4*)&p_xp[o];
#pragma unroll
                for (int w = 1; w < 8; w++) {
                    float4 q2 = *(const float4*)&p_xp[w * 1024 + o];
                    sx.x += q2.x; sx.y += q2.y; sx.z += q2.z; sx.w += q2.w;
                }
                if (s >= 1) {
                    float4 o4;
                    o4.x = sx.x + bias2[0];
                    o4.y = sx.y + bias2[1];
                    o4.z = sx.z + bias2[2];
                    o4.w = sx.w + bias2[3];
                    *(float4*)&xp2[((size_t)(s - 1) * Bdim + eb) * Hdim + j0 + ej]
                        = o4;
                }
            }
            __syncthreads();
            if (s >= 1 && tid == 0)
                asm volatile("red.release.gpu.global.add.u32 [%0], 1;"
                             :: "l"(&g_stepA) : "memory");
            if (s < Sdim) grid_sync_p(&g_barA_cnt, &g_barA_gen, 64);
        }
    } else {
        // ==================== Cohort B: rec1 ====================
        const int j0 = (bid - 64) * 16;
        float* p_s = (float*)(smraw + B_BUF(0));   // partials alias bufs 0/1

        // rec1 W -> temp SMEM, then registers
        for (int i = tid; i < 4096; i += 256) {
            int j = i >> 8;
            int col4 = i & 255;
            uint2 hi, lo;
            split_bf16(*(const float4*)&Whh1[(size_t)(j0 + j) * Hdim + col4 * 4],
                       hi, lo);
            int g = col4 >> 1;
            int off = j * 2048 + ((g ^ (j & 7)) << 4) + (col4 & 1) * 8;
            *(uint2*)(smraw + B_WT_H + off) = hi;
            *(uint2*)(smraw + B_WT_L + off) = lo;
        }
        if (tid < 64) {
            uint4 z = make_uint4(0, 0, 0, 0);
            *(uint4*)&g_hh2[0][(size_t)tid * Hdim + j0] = z;
            *(uint4*)&g_hh2[0][(size_t)tid * Hdim + j0 + 8] = z;
            *(uint4*)&g_hl2[0][(size_t)tid * Hdim + j0] = z;
            *(uint4*)&g_hl2[0][(size_t)tid * Hdim + j0 + 8] = z;
        }
        __syncthreads();

        uint32_t wBh[8][4], wBl[8][4];
#pragma unroll
        for (int c = 0; c < 8; c++) {
            int gB = (c * 8 + wid) * 2 + bck;
            uint32_t sw = (uint32_t)((gB ^ (brow & 7)) << 4);
            ldsm_x4(smem_u32(smraw + B_WT_H) + brow * 2048 + sw, wBh[c]);
            ldsm_x4(smem_u32(smraw + B_WT_L) + brow * 2048 + sw, wBl[c]);
        }
        grid_sync_p(&g_barG_cnt, &g_barG_gen, 128);

#pragma unroll 1
        for (int t = 0; t < Sdim; t++) {
            if (tid == 0) {
                unsigned tgt = 64u * (unsigned)(t + 1);
                unsigned cur;
                do {
                    asm volatile("ld.acquire.gpu.global.u32 %0, [%1];"
                                 : "=r"(cur) : "l"(&g_stepA) : "memory");
                } while (cur < tgt);
            }
            __syncthreads();

            const __nv_bfloat16* hh_in = g_hh2[t & 1];
            const __nv_bfloat16* hl_in = g_hl2[t & 1];
            __nv_bfloat16* hh_out = g_hh2[(t + 1) & 1];
            __nv_bfloat16* hl_out = g_hl2[(t + 1) & 1];

            float4 xpv = *(const float4*)&xp2[((size_t)t * Bdim + eb) * Hdim
                                              + j0 + ej];

            float acc[4][2][4];
#pragma unroll
            for (int mt = 0; mt < 4; mt++)
#pragma unroll
                for (int nt = 0; nt < 2; nt++)
#pragma unroll
                    for (int i = 0; i < 4; i++) acc[mt][nt][i] = 0.0f;

            stage_h128(hh_in, hl_in, 0, smraw + B_BUF(0), tid);
            asm volatile("cp.async.commit_group;");
            stage_h128(hh_in, hl_in, 1, smraw + B_BUF(1), tid);
            asm volatile("cp.async.commit_group;");
            stage_h128(hh_in, hl_in, 2, smraw + B_BUF(2), tid);
            asm volatile("cp.async.commit_group;");

#pragma unroll
            for (int c = 0; c < 8; c++) {
                if (c < 6)       asm volatile("cp.async.wait_group 2;");
                else if (c == 6) asm volatile("cp.async.wait_group 1;");
                else             asm volatile("cp.async.wait_group 0;");
                __syncthreads();

                const uint32_t shb = smem_u32(smraw + B_BUF(c & 3));
                const uint32_t slb = shb + 16384;

                uint32_t ah[4][4], al[4][4];
                int gA = wid * 2 + ack;
#pragma unroll
                for (int mt = 0; mt < 4; mt++) {
                    int row = mt * 16 + arow;
                    uint32_t ph = (uint32_t)((gA & 8) | ((gA ^ (row & 7)) & 7)) << 4;
                    ldsm_x4(shb + row * 256 + ph, ah[mt]);
                    ldsm_x4(slb + row * 256 + ph, al[mt]);
                }
#pragma unroll
                for (int mt = 0; mt < 4; mt++) {
                    mma16816(acc[mt][0], ah[mt], &wBh[c][0]);
                    mma16816(acc[mt][1], ah[mt], &wBh[c][2]);
                    mma16816(acc[mt][0], ah[mt], &wBl[c][0]);
                    mma16816(acc[mt][1], ah[mt], &wBl[c][2]);
                    mma16816(acc[mt][0], al[mt], &wBh[c][0]);
                    mma16816(acc[mt][1], al[mt], &wBh[c][2]);
                }
                if (c + 3 < 8) {
                    stage_h128(hh_in, hl_in, c + 3,
                               smraw + B_BUF((c + 3) & 3), tid);
                    asm volatile("cp.async.commit_group;");
                }
            }

#pragma unroll
            for (int mt = 0; mt < 4; mt++)
#pragma unroll
                for (int nt = 0; nt < 2; nt++) {
                    int b = mt * 16 + (lane >> 2);
                    int j = nt * 8 + (lane & 3) * 2;
                    *(float2*)&p_s[wid * 1024 + b * 16 + j] =
                        make_float2(acc[mt][nt][0], acc[mt][nt][1]);
                    *(float2*)&p_s[wid * 1024 + (b + 8) * 16 + j] =
                        make_float2(acc[mt][nt][2], acc[mt][nt][3]);
                }
            __syncthreads();

            {
                int o = tid * 4;
                float4 s = *(const float4*)&p_s[o];
#pragma unroll
                for (int w = 1; w < 8; w++) {
                    float4 q = *(const float4*)&p_s[w * 1024 + o];
                    s.x += q.x; s.y += q.y; s.z += q.z; s.w += q.w;
                }
                float v0 = tanhf(s.x + xpv.x);
                float v1 = tanhf(s.y + xpv.y);
                float v2 = tanhf(s.z + xpv.z);
                float v3 = tanhf(s.w + xpv.w);
                unsigned h01, l01, h23, l23;
                split2_bf16(v0, v1, h01, l01);
                split2_bf16(v2, v3, h23, l23);
                size_t ho = (size_t)eb * Hdim + j0 + ej;
                *(uint2*)&hh_out[ho] = make_uint2(h01, h23);
                *(uint2*)&hl_out[ho] = make_uint2(l01, l23);
            }
            grid_sync_p(&g_barB_cnt, &g_barB_gen, 64);
        }
    }
}

// ============================================================================
// Final FC + sigmoid: h_last = g_hh2[0] + g_hl2[0]  ((511+1)&1 = 0)
// ============================================================================
__global__ void fc_kernel(const __nv_bfloat16* __restrict__ hh,
                          const __nv_bfloat16* __restrict__ hl,
                          const float* __restrict__ fcw,
                          const float* __restrict__ fcb,
                          float* __restrict__ out)
{
    __shared__ float red[8];
    int b = blockIdx.x, tid = threadIdx.x;
    float s = 0.0f;
    for (int k = tid; k < Hdim; k += 256) {
        float h = __bfloat162float(hh[b * Hdim + k]) +
                  __bfloat162float(hl[b * Hdim + k]);
        s += h * fcw[k];
    }
#pragma unroll
    for (int o = 16; o; o >>= 1) s += __shfl_xor_sync(0xFFFFFFFFu, s, o);
    if ((tid & 31) == 0) red[tid >> 5] = s;
    __syncthreads();
    if (tid == 0) {
        float tot = 0.0f;
#pragma unroll
        for (int i = 0; i < 8; i++) tot += red[i];
        float logit = tot + fcb[0];
        out[b] = 1.0f / (1.0f + expf(-logit));
    }
}

// ============================================================================
extern "C" void kernel_launch(void* const* d_in, const int* in_sizes, int n_in,
                              void* d_out, int out_size)
{
    const float* x     = (const float*)d_in[0];
    const float* W_ih0 = (const float*)d_in[1];
    const float* W_hh0 = (const float*)d_in[2];
    const float* b_ih0 = (const float*)d_in[3];
    const float* b_hh0 = (const float*)d_in[4];
    const float* W_ih1 = (const float*)d_in[5];
    const float* W_hh1 = (const float*)d_in[6];
    const float* b_ih1 = (const float*)d_in[7];
    const float* b_hh1 = (const float*)d_in[8];
    const float* fc_w  = (const float*)d_in[9];
    const float* fc_b  = (const float*)d_in[10];
    float* out = (float*)d_out;

    float *xp, *xp2;
    __nv_bfloat16 *hh2, *hl2;
    cudaGetSymbolAddress((void**)&xp, g_xp);
    cudaGetSymbolAddress((void**)&xp2, g_xp2);
    cudaGetSymbolAddress((void**)&hh2, g_hh2);
    cudaGetSymbolAddress((void**)&hl2, g_hl2);

    cudaFuncSetAttribute(rnn_fused_kernel,
                         cudaFuncAttributeMaxDynamicSharedMemorySize,
                         RNN_SMEM_BYTES);
    cudaFuncSetAttribute(xproj_mma_kernel<Fdim>,
                         cudaFuncAttributeMaxDynamicSharedMemorySize, XP_SMEM);

    dim3 xgrid(8, 256);
    // layer-0 xp: rows m = b*S + t -> xp[(b*S+t)*H + j]
    xproj_mma_kernel<Fdim><<<xgrid, 256, XP_SMEM>>>(x, W_ih0, b_ih0, b_hh0, xp);
    // fused dual-layer recurrence (A: rec0 + xp2; B: rec1)
    rnn_fused_kernel<<<128, 256, RNN_SMEM_BYTES>>>(
        xp, W_hh0, W_ih1, b_ih1, b_hh1, W_hh1, xp2);
    // head: final h2 in slot 0
    fc_kernel<<<64, 256>>>(hh2, hl2, fc_w, fc_b, out);
}